// round 15
// baseline (speedup 1.0000x reference)
#include <cuda_runtime.h>
#include <cuda_bf16.h>
#include <math_constants.h>

typedef unsigned long long u64;
typedef unsigned short u16;
typedef unsigned int u32;

__device__ __forceinline__ u64 pk(float lo, float hi) {
    u64 r;
    asm("mov.b64 %0, {%1, %2};" : "=l"(r) : "f"(lo), "f"(hi));
    return r;
}
__device__ __forceinline__ void upk(u64 v, float& lo, float& hi) {
    asm("mov.b64 {%0, %1}, %2;" : "=f"(lo), "=f"(hi) : "l"(v));
}
__device__ __forceinline__ void fma2(u64& d, u64 a, u64 b) {
    asm("fma.rn.f32x2 %0, %1, %2, %0;" : "+l"(d) : "l"(a), "l"(b));
}
__device__ __forceinline__ unsigned s2u(const void* p) {
    return (unsigned)__cvta_generic_to_shared(p);
}
__device__ __forceinline__ void cpa4(unsigned saddr, const float* g, bool v) {
    int sz = v ? 4 : 0;
    asm volatile("cp.async.ca.shared.global [%0], [%1], 4, %2;"
                 :: "r"(saddr), "l"(g), "r"(sz) : "memory");
}
__device__ __forceinline__ void cpa16(unsigned saddr, const void* g) {
    asm volatile("cp.async.cg.shared.global [%0], [%1], 16;"
                 :: "r"(saddr), "l"(g) : "memory");
}
#define CP_COMMIT() asm volatile("cp.async.commit_group;" ::: "memory")
#define CP_WAIT0()  asm volatile("cp.async.wait_group 0;" ::: "memory")

// warp-level bf16 MMA (sm_80+ baseline PTX)
__device__ __forceinline__ void mma16816(float* c, const u32* a, const u32* b) {
    asm volatile(
        "mma.sync.aligned.m16n8k16.row.col.f32.bf16.bf16.f32 "
        "{%0,%1,%2,%3}, {%4,%5,%6,%7}, {%8,%9}, {%0,%1,%2,%3};"
        : "+f"(c[0]), "+f"(c[1]), "+f"(c[2]), "+f"(c[3])
        : "r"(a[0]), "r"(a[1]), "r"(a[2]), "r"(a[3]), "r"(b[0]), "r"(b[1]));
}

// Scratch buffers
__device__ float g_a1[128 * 64 * 64 * 64];
__device__ float g_a2[128 * 128 * 32 * 32];
__device__ float g_a3[128 * 192 * 16 * 16];
__device__ float g_h4[128 * 256 * 16 * 16];
__device__ float g_hq[128 * 256 * 16 * 16];
__device__ float g_d1[128 * 192 * 16 * 16];
__device__ float g_d2[128 * 128 * 32 * 32];
__device__ float g_d3[128 * 64 * 64 * 64];
__device__ float g_scale[256];
__device__ float g_shift[256];
__device__ float g_lossp[32768];
__device__ float g_cc[256];
__device__ float g_wt2[64 * 16 * 128];
__device__ float g_wt3[128 * 16 * 192];
// bf16 hi/lo planes
__device__ u16 g_b1h[128 * 192 * 256];
__device__ u16 g_b1l[128 * 192 * 256];
__device__ u16 g_b2h[128 * 128 * 1024];
__device__ u16 g_b2l[128 * 128 * 1024];
// MMA weights
__device__ u16 g_wbh[4 * 8 * 4096];
__device__ u16 g_wbl[4 * 8 * 4096];
__device__ u16 g_w2bh[4 * 12 * 8192];
__device__ u16 g_w2bl[4 * 12 * 8192];

__global__ void wtr_fwd_k(const float* __restrict__ w, float* __restrict__ wt,
                          int Cin, int Cout)
{
    int i = blockIdx.x * 256 + threadIdx.x;
    int total = Cin * Cout * 16;
    if (i >= total) return;
    int oc = i % Cout; int r = i / Cout;
    int t = r & 15; int ic = r >> 4;
    wt[i] = w[((long)oc * Cin + ic) * 16 + t];
}

// d3 weights -> per (cls,chunk) [64 oc][64 k]
__global__ void wsplit3n_k(const float* __restrict__ w, u16* __restrict__ wbh,
                           u16* __restrict__ wbl)
{
    int i = blockIdx.x * 256 + threadIdx.x;
    if (i >= 4 * 8 * 16 * 4 * 64) return;
    int oc  = i & 63;
    int t   = (i >> 6) & 3;
    int icl = (i >> 8) & 15;
    int cc  = (i >> 12) & 7;
    int cls = i >> 15;
    int a = cls >> 1, b = cls & 1;
    int ic = cc * 16 + icl;
    float v = w[((long)ic * 64 + oc) * 16
                + (1 - a + 2 * (t >> 1)) * 4 + (1 - b + 2 * (t & 1))];
    __nv_bfloat16 h = __float2bfloat16(v);
    float hf = __bfloat162float(h);
    __nv_bfloat16 l = __float2bfloat16(v - hf);
    int idx = (cls * 8 + cc) * 4096 + oc * 64 + (icl * 4 + t);
    wbh[idx] = __bfloat16_as_ushort(h);
    wbl[idx] = __bfloat16_as_ushort(l);
}

// d2 weights -> per (cls,chunk12) [128 oc][64 k]
__global__ void wsplit2n_k(const float* __restrict__ w, u16* __restrict__ wbh,
                           u16* __restrict__ wbl)
{
    int i = blockIdx.x * 256 + threadIdx.x;
    if (i >= 4 * 12 * 16 * 4 * 128) return;
    int oc  = i & 127;
    int t   = (i >> 7) & 3;
    int icl = (i >> 9) & 15;
    int cc  = (i >> 13) % 12;
    int cls = i / (12 * 8192);
    int a = cls >> 1, b = cls & 1;
    int ic = cc * 16 + icl;
    float v = w[((long)ic * 128 + oc) * 16
                + (1 - a + 2 * (t >> 1)) * 4 + (1 - b + 2 * (t & 1))];
    __nv_bfloat16 h = __float2bfloat16(v);
    float hf = __bfloat162float(h);
    __nv_bfloat16 l = __float2bfloat16(v - hf);
    int idx = (cls * 12 + cc) * 8192 + oc * 64 + (icl * 4 + t);
    wbh[idx] = __bfloat16_as_ushort(h);
    wbl[idx] = __bfloat16_as_ushort(l);
}

// BN apply + ReLU + bf16 hi/lo split
__global__ void bn_apply_split_k(const float2* __restrict__ x,
                                 const float* __restrict__ scale,
                                 const float* __restrict__ shift,
                                 u32* __restrict__ hi, u32* __restrict__ lo,
                                 int C, int hwsh, int total2)
{
    int i = blockIdx.x * 256 + threadIdx.x;
    if (i >= total2) return;
    int c = ((i * 2) >> hwsh) % C;
    float s = scale[c], t = shift[c];
    float2 v = x[i];
    float v0 = fmaxf(fmaf(v.x, s, t), 0.f);
    float v1 = fmaxf(fmaf(v.y, s, t), 0.f);
    __nv_bfloat16 h0 = __float2bfloat16(v0);
    __nv_bfloat16 h1 = __float2bfloat16(v1);
    __nv_bfloat16 l0 = __float2bfloat16(v0 - __bfloat162float(h0));
    __nv_bfloat16 l1 = __float2bfloat16(v1 - __bfloat162float(h1));
    hi[i] = (u32)__bfloat16_as_ushort(h0) | ((u32)__bfloat16_as_ushort(h1) << 16);
    lo[i] = (u32)__bfloat16_as_ushort(l0) | ((u32)__bfloat16_as_ushort(l1) << 16);
}

// ---------------------------------------------------------------------------
// d3 via warp mma bf16-split (proven).
// ---------------------------------------------------------------------------
__global__ void __launch_bounds__(256)
convt_mma_k(const u16* __restrict__ b2h, const u16* __restrict__ b2l,
            const u16* __restrict__ wbh, const u16* __restrict__ wbl,
            const float* __restrict__ bias, float* __restrict__ out)
{
    __shared__ u32 sBh[64 * 36];
    __shared__ u32 sBl[64 * 36];
    __shared__ u32 sRH[1280];
    __shared__ u32 sRL[1280];

    int tid = threadIdx.x;
    int wrp = tid >> 5, lane = tid & 31;
    int g = lane >> 2, tq = lane & 3;
    int pxt = blockIdx.x;
    int n   = blockIdx.y;
    int cls = blockIdx.z;
    int a = cls >> 1, b = cls & 1;
    int s0 = pxt * 4;
    int rb = wrp * 16;

    float acc[8][4];
#pragma unroll
    for (int nt = 0; nt < 8; nt++)
#pragma unroll
        for (int r = 0; r < 4; r++) acc[nt][r] = 0.f;

    long nbase = (long)n << 17;
    const u16* rawh = (const u16*)sRH;
    const u16* rawl = (const u16*)sRL;

    auto afrag = [&](const u16* raw, int pos, int k) -> u32 {
        int sr = pos >> 5, c = pos & 31;
        int icl = k >> 2, t = k & 3;
        int ty = t >> 1;
        const u16* rowp = raw + (icl * 5 + (sr + 1 - ty)) * 32;
        int xa = c + b;
        u32 v0 = (xa < 32) ? (u32)rowp[xa] : 0u;
        u32 v1 = (xa >= 1) ? (u32)rowp[xa - 1] : 0u;
        return v0 | (v1 << 16);
    };

    for (int cc = 0; cc < 8; cc++) {
        __syncthreads();
        {
            const u16* gh = wbh + (cls * 8 + cc) * 4096;
            const u16* gl = wbl + (cls * 8 + cc) * 4096;
            for (int i = tid; i < 2048; i += 256) {
                int k2 = i & 31, oc = i >> 5;
                sBh[oc * 36 + k2] = *(const u32*)(gh + oc * 64 + 2 * k2);
                sBl[oc * 36 + k2] = *(const u32*)(gl + oc * 64 + 2 * k2);
            }
            for (int i = tid; i < 1280; i += 256) {
                int x2 = i & 15;
                int j = (i >> 4) % 5;
                int icl = i / 80;
                int y = s0 + a - 1 + j;
                u32 vh = 0u, vl = 0u;
                if ((unsigned)y < 32u) {
                    long off = nbase + ((long)(cc * 16 + icl) << 10) + y * 32 + 2 * x2;
                    vh = *(const u32*)(b2h + off);
                    vl = *(const u32*)(b2l + off);
                }
                sRH[(icl * 5 + j) * 16 + x2] = vh;
                sRL[(icl * 5 + j) * 16 + x2] = vl;
            }
            __syncthreads();
        }

        u32 AH[4][4], AL[4][4];
#pragma unroll
        for (int ks = 0; ks < 4; ks++) {
            int k0 = ks * 16 + 2 * tq;
            AH[ks][0] = afrag(rawh, rb + g, k0);
            AH[ks][1] = afrag(rawh, rb + g + 8, k0);
            AH[ks][2] = afrag(rawh, rb + g, k0 + 8);
            AH[ks][3] = afrag(rawh, rb + g + 8, k0 + 8);
            AL[ks][0] = afrag(rawl, rb + g, k0);
            AL[ks][1] = afrag(rawl, rb + g + 8, k0);
            AL[ks][2] = afrag(rawl, rb + g, k0 + 8);
            AL[ks][3] = afrag(rawl, rb + g + 8, k0 + 8);
        }

#pragma unroll
        for (int nt = 0; nt < 8; nt++) {
            int oc = nt * 8 + g;
#pragma unroll
            for (int ks = 0; ks < 4; ks++) {
                u32 bh[2], bl[2];
                bh[0] = sBh[oc * 36 + ks * 8 + tq];
                bh[1] = sBh[oc * 36 + ks * 8 + tq + 4];
                bl[0] = sBl[oc * 36 + ks * 8 + tq];
                bl[1] = sBl[oc * 36 + ks * 8 + tq + 4];
                mma16816(acc[nt], AH[ks], bh);
                mma16816(acc[nt], AH[ks], bl);
                mma16816(acc[nt], AL[ks], bh);
            }
        }
    }

#pragma unroll
    for (int nt = 0; nt < 8; nt++) {
        int oc0 = nt * 8 + 2 * tq;
        float b0 = bias[oc0], b1 = bias[oc0 + 1];
#pragma unroll
        for (int rh = 0; rh < 2; rh++) {
            int pos = rb + g + rh * 8;
            int sr = pos >> 5, c = pos & 31;
            int oy = 2 * (s0 + sr) + a;
            int ox = 2 * c + b;
            long ob = (((long)n * 64 + oc0) * 64 + oy) * 64 + ox;
            out[ob] = acc[nt][rh * 2] + b0;
            out[ob + 4096] = acc[nt][rh * 2 + 1] + b1;
        }
    }
}

// ---------------------------------------------------------------------------
// d2 via warp mma bf16-split (proven).
// ---------------------------------------------------------------------------
__global__ void __launch_bounds__(256)
convt_mma2_k(const u16* __restrict__ b1h, const u16* __restrict__ b1l,
             const u16* __restrict__ wbh, const u16* __restrict__ wbl,
             const float* __restrict__ bias, float* __restrict__ out)
{
    __shared__ u32 sBh[128 * 33];
    __shared__ u32 sBl[128 * 33];
    __shared__ u32 sRH[16 * 9 * 8];
    __shared__ u32 sRL[16 * 9 * 8];

    int tid = threadIdx.x;
    int wrp = tid >> 5, lane = tid & 31;
    int g = lane >> 2, tq = lane & 3;
    int pxt = blockIdx.x;
    int n   = blockIdx.y;
    int cls = blockIdx.z;
    int a = cls >> 1, b = cls & 1;
    int s0 = pxt * 8;
    int rb = wrp * 16;

    float acc[16][4];
#pragma unroll
    for (int nt = 0; nt < 16; nt++)
#pragma unroll
        for (int r = 0; r < 4; r++) acc[nt][r] = 0.f;

    long nbase = (long)n * 192 * 256;
    const u16* rawh = (const u16*)sRH;
    const u16* rawl = (const u16*)sRL;

    auto afrag = [&](const u16* raw, int pos, int k) -> u32 {
        int sr = pos >> 4, c = pos & 15;
        int icl = k >> 2, t = k & 3;
        int ty = t >> 1;
        const u16* rowp = raw + (icl * 9 + (sr + 1 - ty)) * 16;
        int xa = c + b;
        u32 v0 = (xa < 16) ? (u32)rowp[xa] : 0u;
        u32 v1 = (xa >= 1) ? (u32)rowp[xa - 1] : 0u;
        return v0 | (v1 << 16);
    };

    for (int cc = 0; cc < 12; cc++) {
        __syncthreads();
        {
            const u16* gh = wbh + (cls * 12 + cc) * 8192;
            const u16* gl = wbl + (cls * 12 + cc) * 8192;
            for (int i = tid; i < 4096; i += 256) {
                int k2 = i & 31, oc = i >> 5;
                sBh[oc * 33 + k2] = *(const u32*)(gh + oc * 64 + 2 * k2);
                sBl[oc * 33 + k2] = *(const u32*)(gl + oc * 64 + 2 * k2);
            }
            for (int i = tid; i < 1152; i += 256) {
                int x2 = i & 7;
                int j = (i >> 3) % 9;
                int icl = i / 72;
                int y = s0 + a - 1 + j;
                u32 vh = 0u, vl = 0u;
                if ((unsigned)y < 16u) {
                    long off = nbase + (long)(cc * 16 + icl) * 256 + y * 16 + 2 * x2;
                    vh = *(const u32*)(b1h + off);
                    vl = *(const u32*)(b1l + off);
                }
                sRH[(icl * 9 + j) * 8 + x2] = vh;
                sRL[(icl * 9 + j) * 8 + x2] = vl;
            }
            __syncthreads();
        }

        u32 AH[4][4], AL[4][4];
#pragma unroll
        for (int ks = 0; ks < 4; ks++) {
            int k0 = ks * 16 + 2 * tq;
            AH[ks][0] = afrag(rawh, rb + g, k0);
            AH[ks][1] = afrag(rawh, rb + g + 8, k0);
            AH[ks][2] = afrag(rawh, rb + g, k0 + 8);
            AH[ks][3] = afrag(rawh, rb + g + 8, k0 + 8);
            AL[ks][0] = afrag(rawl, rb + g, k0);
            AL[ks][1] = afrag(rawl, rb + g + 8, k0);
            AL[ks][2] = afrag(rawl, rb + g, k0 + 8);
            AL[ks][3] = afrag(rawl, rb + g + 8, k0 + 8);
        }

#pragma unroll
        for (int nt = 0; nt < 16; nt++) {
            int oc = nt * 8 + g;
#pragma unroll
            for (int ks = 0; ks < 4; ks++) {
                u32 bh[2], bl[2];
                bh[0] = sBh[oc * 33 + ks * 8 + tq];
                bh[1] = sBh[oc * 33 + ks * 8 + tq + 4];
                bl[0] = sBl[oc * 33 + ks * 8 + tq];
                bl[1] = sBl[oc * 33 + ks * 8 + tq + 4];
                mma16816(acc[nt], AH[ks], bh);
                mma16816(acc[nt], AH[ks], bl);
                mma16816(acc[nt], AL[ks], bh);
            }
        }
    }

#pragma unroll
    for (int nt = 0; nt < 16; nt++) {
        int oc0 = nt * 8 + 2 * tq;
        float b0 = bias[oc0], b1 = bias[oc0 + 1];
#pragma unroll
        for (int rh = 0; rh < 2; rh++) {
            int pos = rb + g + rh * 8;
            int sr = pos >> 4, c = pos & 15;
            int oy = 2 * (s0 + sr) + a;
            int ox = 2 * c + b;
            long ob = (((long)n * 128 + oc0) * 32 + oy) * 32 + ox;
            out[ob] = acc[nt][rh * 2] + b0;
            out[ob + 1024] = acc[nt][rh * 2 + 1] + b1;
        }
    }
}

// ---------------------------------------------------------------------------
// k4 s2 p1 forward conv, oc-packed fma2, cp.async (round 7, unchanged).
// ---------------------------------------------------------------------------
template <int COLS, int RB, int ICT>
__global__ void __launch_bounds__(256, 2)
convf3_k(const float* __restrict__ in, const float* __restrict__ wt,
         const float* __restrict__ bias, float* __restrict__ out,
         int Cin, int Cout, int npx)
{
    constexpr int HL = 32 / COLS;
    constexpr int RT = RB / (2 * HL);
    constexpr int SROWS = 2 * RB + 2;
    constexpr int SLOTW = 2 * COLS + 2;
    constexpr int SU = ICT * SROWS * SLOTW;
    constexpr int SW = ICT * 16 * 64;
    constexpr int BUF = SU + SW;
    extern __shared__ float smdyn[];

    const int Win = 2 * COLS, Hin = 2 * COLS;

    int n   = blockIdx.y;
    int pxt = blockIdx.x % npx;
    int oct = blockIdx.x / npx;
    int tid = threadIdx.x;
    int wrp = tid >> 5, lane = tid & 31;
    int og = wrp >> 1, rg = wrp & 1;
    int c  = lane % COLS, h = lane / COLS;
    int oy0 = pxt * RB;
    int ocb = oct * 64 + og * 16;
    int rl0 = rg * (RB / 2) + h * RT;

    u64 acc[8][RT];
#pragma unroll
    for (int j = 0; j < 8; j++) {
        u64 b2 = pk(bias[ocb + 2 * j], bias[ocb + 2 * j + 1]);
#pragma unroll
        for (int i = 0; i < RT; i++) acc[j][i] = b2;
    }

    auto stage = [&](int ic0, float* buf) {
        unsigned su_s = s2u(buf);
        unsigned sw_s = s2u(buf + SU);
        const float* ibase = in + ((long)n * Cin + ic0) * (long)(Hin * Win);
        for (int i = tid; i < SU; i += 256) {
            int s = i % SLOTW;
            int j = (i / SLOTW) % SROWS;
            int icl = i / (SLOTW * SROWS);
            int x = s - 1;
            int iy = 2 * oy0 - 1 + j;
            bool vld = (unsigned)x < (unsigned)Win && (unsigned)iy < (unsigned)Hin;
            const float* gp = vld ? ibase + (long)icl * (Hin * Win) + iy * Win + x
                                  : ibase;
            cpa4(su_s + i * 4, gp, vld);
        }
        for (int i4 = tid; i4 < SW / 4; i4 += 256) {
            int i = i4 * 4;
            int oc = i & 63;
            int row = i >> 6;
            const float* gp = wt + ((long)(ic0 * 16 + row)) * Cout + oct * 64 + oc;
            cpa16(sw_s + i * 4, gp);
        }
    };

    auto compute = [&](const float* buf) {
        const float* su = buf;
        const float* swp = buf + SU;
#pragma unroll 1
        for (int icl = 0; icl < ICT; icl++) {
#pragma unroll
            for (int ky = 0; ky < 4; ky++) {
                u64 qd[RT][4];
#pragma unroll
                for (int i = 0; i < RT; i++) {
                    const float* row = su + (icl * SROWS + 2 * (rl0 + i) + ky) * SLOTW + 2 * c;
                    float2 f01 = *(const float2*)(row);
                    float2 f23 = *(const float2*)(row + 2);
                    qd[i][0] = pk(f01.x, f01.x);
                    qd[i][1] = pk(f01.y, f01.y);
                    qd[i][2] = pk(f23.x, f23.x);
                    qd[i][3] = pk(f23.y, f23.y);
                }
#pragma unroll
                for (int kx = 0; kx < 4; kx++) {
                    const ulonglong2* wp =
                        (const ulonglong2*)(swp + (icl * 16 + ky * 4 + kx) * 64 + og * 16);
                    ulonglong2 w01 = wp[0];
                    ulonglong2 w23 = wp[1];
                    ulonglong2 w45 = wp[2];
                    ulonglong2 w67 = wp[3];
#pragma unroll
                    for (int i = 0; i < RT; i++) {
                        fma2(acc[0][i], qd[i][kx], w01.x);
                        fma2(acc[1][i], qd[i][kx], w01.y);
                        fma2(acc[2][i], qd[i][kx], w23.x);
                        fma2(acc[3][i], qd[i][kx], w23.y);
                        fma2(acc[4][i], qd[i][kx], w45.x);
                        fma2(acc[5][i], qd[i][kx], w45.y);
                        fma2(acc[6][i], qd[i][kx], w67.x);
                        fma2(acc[7][i], qd[i][kx], w67.y);
                    }
                }
            }
        }
    };

    float* buf0 = smdyn;
    float* buf1 = smdyn + BUF;
    stage(0, buf0);
    CP_COMMIT();
    CP_WAIT0();
    __syncthreads();
    int nch = Cin / ICT;
    for (int ch = 0; ch < nch; ch++) {
        float* cbuf = (ch & 1) ? buf1 : buf0;
        float* nbuf = (ch & 1) ? buf0 : buf1;
        if (ch + 1 < nch) { stage((ch + 1) * ICT, nbuf); CP_COMMIT(); }
        compute(cbuf);
        if (ch + 1 < nch) { CP_WAIT0(); __syncthreads(); }
    }

#pragma unroll
    for (int j = 0; j < 8; j++) {
#pragma unroll
        for (int i = 0; i < RT; i++) {
            float lo, hi;
            upk(acc[j][i], lo, hi);
            long o0 = ((long)n * Cout + ocb + 2 * j) * (COLS * COLS)
                    + (oy0 + rl0 + i) * COLS + c;
            out[o0] = lo;
            out[o0 + COLS * COLS] = hi;
        }
    }
}

// ---------------------------------------------------------------------------
// conv1 (3->64 k3 s1 p1): smem-staged, column-pair fma2 (cols c, c+32).
// Chain per output: bias; (ic asc, ky asc, kx asc); zero borders — bit-exact.
// Block: 4 out rows x 64 cols x 64 oc. Grid (16 rowtiles, 128 imgs).
// ---------------------------------------------------------------------------
__global__ void __launch_bounds__(256)
convf1_k(const float* __restrict__ in, const float* __restrict__ w,
         const float* __restrict__ bias, float* __restrict__ out)
{
    __shared__ u64 pu[3 * 6 * 34];     // {x[t-1], x[t+31]} per (ic,row)
    __shared__ u64 sw[3 * 64 * 12];    // {w,w}

    int n = blockIdx.y;
    int rt0 = blockIdx.x * 4;
    int tid = threadIdx.x;
    int wrp = tid >> 5, lane = tid & 31;
    int ocb = wrp * 8;

    for (int i = tid; i < 3 * 64 * 12; i += 256) sw[i] = 0ull;
    __syncthreads();
    for (int i = tid; i < 3 * 64 * 9; i += 256) {
        int kk = i % 9; int oc = (i / 9) % 64; int ic = i / (9 * 64);
        float v = w[((long)oc * 3 + ic) * 9 + kk];
        sw[(ic * 64 + oc) * 12 + (kk / 3) * 4 + kk % 3] = pk(v, v);
    }
    const float* ib = in + (long)n * 3 * 4096;
    for (int i = tid; i < 3 * 6 * 34; i += 256) {
        int t = i % 34; int r = (i / 34) % 6; int ic = i / (34 * 6);
        int gy = rt0 - 1 + r;
        bool yv = (unsigned)gy < 64u;
        float lo = (yv && t >= 1) ? ib[ic * 4096 + gy * 64 + t - 1] : 0.f;
        float hi = (yv && t <= 32) ? ib[ic * 4096 + gy * 64 + t + 31] : 0.f;
        pu[i] = pk(lo, hi);
    }
    __syncthreads();

    u64 acc[8][4];
#pragma unroll
    for (int o = 0; o < 8; o++) {
        float b = bias[ocb + o];
#pragma unroll
        for (int r = 0; r < 4; r++) acc[o][r] = pk(b, b);
    }

#pragma unroll
    for (int ic = 0; ic < 3; ic++) {
#pragma unroll
        for (int ky = 0; ky < 3; ky++) {
            u64 q[4][3];
#pragma unroll
            for (int r = 0; r < 4; r++) {
                const u64* rowp = pu + (ic * 6 + r + ky) * 34 + lane;
                q[r][0] = rowp[0];
                q[r][1] = rowp[1];
                q[r][2] = rowp[2];
            }
#pragma unroll
            for (int o = 0; o < 8; o++) {
                const u64* wb = sw + (ic * 64 + ocb + o) * 12 + ky * 4;
                ulonglong2 w01 = ((const ulonglong2*)wb)[0];
                u64 w2 = wb[2];
#pragma unroll
                for (int r = 0; r < 4; r++) {
                    fma2(acc[o][r], q[r][0], w01.x);
                    fma2(acc[o][r], q[r][1], w01.y);
                    fma2(acc[o][r], q[r][2], w2);
                }
            }
        }
    }

#pragma unroll
    for (int o = 0; o < 8; o++) {
#pragma unroll
        for (int r = 0; r < 4; r++) {
            float lo, hi;
            upk(acc[o][r], lo, hi);
            long ob = (((long)n * 64 + ocb + o) * 64 + rt0 + r) * 64 + lane;
            out[ob] = lo;
            out[ob + 32] = hi;
        }
    }
}

// ---------------------------------------------------------------------------
// Final conv 64 -> 3, k3 s1 p1, smem-staged + cp.async, row-pair fma2
// (round-7 kernel; bit-exactness verified by the R8 run's unchanged rel_err).
// ---------------------------------------------------------------------------
__global__ void __launch_bounds__(256, 3)
convlast2_k(const float* __restrict__ in, const float* __restrict__ w,
            const float* __restrict__ bias, float* __restrict__ out)
{
    constexpr int ICT = 8;
    constexpr int SROWS = 10;
    constexpr int SLOTW = 66;
    constexpr int SU = ICT * SROWS * SLOTW;
    extern __shared__ float smdyn[];
    __shared__ u64 ws2[64 * 3 * 12];

    int n  = blockIdx.y;
    int r0 = blockIdx.x * 8;
    int tid = threadIdx.x;
    int x  = tid & 63;
    int rq = tid >> 6;

    for (int i = tid; i < 64 * 3 * 12; i += 256) ws2[i] = 0ull;
    __syncthreads();
    for (int i = tid; i < 64 * 3 * 9; i += 256) {
        int kk = i % 9; int t = i / 9; int oc = t % 3; int ic = t / 3;
        float v = w[((long)oc * 64 + ic) * 9 + kk];
        ws2[((ic * 3 + oc) * 3 + kk / 3) * 4 + kk % 3] = pk(v, v);
    }

    u64 acc[3];
#pragma unroll
    for (int o = 0; o < 3; o++) {
        float b = bias[o];
        acc[o] = pk(b, b);
    }

    const float* ib = in + (long)n * 64 * 4096;

    auto stage = [&](int ic0, float* buf) {
        unsigned su_s = s2u(buf);
        for (int i = tid; i < SU; i += 256) {
            int s = i % SLOTW;
            int j = (i / SLOTW) % SROWS;
            int icl = i / (SLOTW * SROWS);
            int xx = s - 1;
            int iy = r0 - 1 + j;
            bool vld = (unsigned)xx < 64u && (unsigned)iy < 64u;
            const float* gp = vld ? ib + (long)(ic0 + icl) * 4096 + iy * 64 + xx : ib;
            cpa4(su_s + i * 4, gp, vld);
        }
    };

    auto compute = [&](const float* su, int ic0) {
#pragma unroll 1
        for (int icl = 0; icl < ICT; icl++) {
            int ic = ic0 + icl;
#pragma unroll
            for (int ky = 0; ky < 3; ky++) {
                const float* rl = su + (icl * SROWS + rq + ky) * SLOTW + x;
                const float* rh = su + (icl * SROWS + rq + 4 + ky) * SLOTW + x;
                float a0 = rl[0], a1 = rl[1], a2 = rl[2];
                float b0 = rh[0], b1 = rh[1], b2 = rh[2];
                u64 q0 = pk(a0, b0), q1 = pk(a1, b1), q2 = pk(a2, b2);
#pragma unroll
                for (int o = 0; o < 3; o++) {
                    const u64* wb = ws2 + ((ic * 3 + o) * 3 + ky) * 4;
                    ulonglong2 w01 = ((const ulonglong2*)wb)[0];
                    u64 w2 = wb[2];
                    fma2(acc[o], q0, w01.x);
                    fma2(acc[o], q1, w01.y);
                    fma2(acc[o], q2, w2);
                }
            }
        }
    };

    float* buf0 = smdyn;
    float* buf1 = smdyn + SU;
    stage(0, buf0);
    CP_COMMIT();
    CP_WAIT0();
    __syncthreads();
    const int nch = 64 / ICT;
    for (int ch = 0; ch < nch; ch++) {
        float* cbuf = (ch & 1) ? buf1 : buf0;
        float* nbuf = (ch & 1) ? buf0 : buf1;
        if (ch + 1 < nch) { stage((ch + 1) * ICT, nbuf); CP_COMMIT(); }
        compute(cbuf, ch * ICT);
        if (ch + 1 < nch) { CP_WAIT0(); __syncthreads(); }
    }

#pragma unroll
    for (int o = 0; o < 3; o++) {
        float lo, hi;
        upk(acc[o], lo, hi);
        long ob = ((long)n * 3 + o) * 4096 + (r0 + rq) * 64 + x;
        out[ob] = lo;
        out[ob + 4 * 64] = hi;
    }
}

// ---------------------------------------------------------------------------
// 1x1 conv / convT as GEMM (round-7 version).
// ---------------------------------------------------------------------------
template <int ICT, bool TRANS>
__global__ void __launch_bounds__(256)
gemm1x1_k(const float* __restrict__ in, const float* __restrict__ w,
          const float* __restrict__ bias, float* __restrict__ out,
          int Cin, int HW, int Cout, int npx)
{
    __shared__ u64 ws2[ICT * 64];
    int n = blockIdx.y;
    int pxt = blockIdx.x % npx, oct = blockIdx.x / npx;
    int tid = threadIdx.x;
    int g = tid >> 5, lane = tid & 31;
    int hw0 = pxt * 128 + lane * 4;
    int ocb = oct * 64 + g * 8;

    u64 acc[8][2];
#pragma unroll
    for (int o = 0; o < 8; o++) {
        float b = bias[ocb + o];
        acc[o][0] = pk(b, b);
        acc[o][1] = pk(b, b);
    }

    long inb = (long)n * Cin * HW + hw0;

    for (int ic0 = 0; ic0 < Cin; ic0 += ICT) {
        __syncthreads();
        for (int i = tid; i < ICT * 64; i += 256) {
            int oc = i & 63, ic = i >> 6;
            float v = TRANS ? w[(long)(ic0 + ic) * Cout + oct * 64 + oc]
                            : w[(long)(oct * 64 + oc) * Cin + ic0 + ic];
            ws2[i] = pk(v, v);
        }
        __syncthreads();

        for (int ic = 0; ic < ICT; ic++) {
            float4 v = *(const float4*)(in + inb + (long)(ic0 + ic) * HW);
            u64 U0 = pk(v.x, v.y), U1 = pk(v.z, v.w);
            const ulonglong2* wp = (const ulonglong2*)(ws2 + ic * 64 + g * 8);
#pragma unroll
            for (int k = 0; k < 4; k++) {
                ulonglong2 ww = wp[k];
                fma2(acc[2 * k][0], U0, ww.x);     fma2(acc[2 * k][1], U1, ww.x);
                fma2(acc[2 * k + 1][0], U0, ww.y); fma2(acc[2 * k + 1][1], U1, ww.y);
            }
        }
    }

    long ob = ((long)n * Cout + ocb) * HW + hw0;
#pragma unroll
    for (int o = 0; o < 8; o++) {
        float4 v;
        upk(acc[o][0], v.x, v.y);
        upk(acc[o][1], v.z, v.w);
        *(float4*)(out + ob + (long)o * HW) = v;
    }
}

// ---------------------------------------------------------------------------
// BatchNorm stats (bit-identical scale/shift).
// ---------------------------------------------------------------------------
__global__ void bn_stats_k(const float* __restrict__ x, const float* __restrict__ g,
                           const float* __restrict__ be, float* __restrict__ scale,
                           float* __restrict__ shift, int C, int N, int HW)
{
    int c = blockIdx.x;
    int tid = threadIdx.x;
    float s = 0.f, ss = 0.f;
    for (int n = 0; n < N; n++) {
        const float* p = x + ((long)(n * C + c)) * HW;
        for (int r = tid; r < HW; r += blockDim.x) {
            float v = p[r];
            s += v; ss += v * v;
        }
    }
    __shared__ float sh1[1024];
    __shared__ float sh2[1024];
    sh1[tid] = s; sh2[tid] = ss;
    __syncthreads();
    for (int ofs = blockDim.x >> 1; ofs > 0; ofs >>= 1) {
        if (tid < ofs) { sh1[tid] += sh1[tid + ofs]; sh2[tid] += sh2[tid + ofs]; }
        __syncthreads();
    }
    if (tid == 0) {
        float cnt = (float)N * (float)HW;
        float m = sh1[0] / cnt;
        float var = sh2[0] / cnt - m * m;
        float sc = g[c] * rsqrtf(var + 1e-5f);
        scale[c] = sc;
        shift[c] = be[c] - m * sc;
    }
}

__global__ void bn_apply4_k(float4* __restrict__ x, const float* __restrict__ scale,
                            const float* __restrict__ shift, int C, int hwsh, int total4)
{
    int i = blockIdx.x * blockDim.x + threadIdx.x;
    if (i >= total4) return;
    int c = (i >> hwsh) % C;
    float s = scale[c], t = shift[c];
    float4 v = x[i];
    v.x = fmaxf(fmaf(v.x, s, t), 0.f);
    v.y = fmaxf(fmaf(v.y, s, t), 0.f);
    v.z = fmaxf(fmaf(v.z, s, t), 0.f);
    v.w = fmaxf(fmaf(v.w, s, t), 0.f);
    x[i] = v;
}

__global__ void cc_k(const float* __restrict__ cb, float* __restrict__ cc)
{
    int j = blockIdx.x * blockDim.x + threadIdx.x;
    if (j >= 256) return;
    double s = 0.0;
    const float* row = cb + (long)j * 256;
    for (int d = 0; d < 256; d++) {
        double v = (double)row[d];
        s += v * v;
    }
    cc[j] = (float)s;
}

// ---------------------------------------------------------------------------
// VQ with reference-exact fp32 distance emulation (unchanged).
// ---------------------------------------------------------------------------
__global__ void vq_exact_k(const float* __restrict__ h, const float* __restrict__ cb,
                           const float* __restrict__ cc, float* __restrict__ hq,
                           float* __restrict__ lossp)
{
    const int POS = 64;
    int b = blockIdx.x >> 2;
    int hw0 = (blockIdx.x & 3) * POS;
    int p = threadIdx.x;

    __shared__ float zs[256 * POS];
    __shared__ float cbs[8 * 256];
    __shared__ float ccs[8];

    const float* hb = h + (long)b * 256 * 256 + hw0;
    for (int d = 0; d < 256; d++)
        zs[d * POS + p] = hb[d * 256 + p];
    __syncthreads();

    float zz = 0.f;
    for (int d = 0; d < 256; d++) {
        float z = zs[d * POS + p];
        zz = fmaf(z, z, zz);
    }

    float best = CUDART_INF_F;
    int bj = 0;

    for (int jc = 0; jc < 256; jc += 8) {
        __syncthreads();
        for (int t = p; t < 8 * 256; t += POS)
            cbs[t] = cb[jc * 256 + t];
        if (p < 8) ccs[p] = cc[jc + p];
        __syncthreads();

        float acc[8];
#pragma unroll
        for (int q = 0; q < 8; q++) acc[q] = 0.f;

        for (int dc = 0; dc < 256; dc += 32) {
            float zreg[32];
#pragma unroll
            for (int d = 0; d < 32; d++)
                zreg[d] = zs[(dc + d) * POS + p];
#pragma unroll
            for (int q = 0; q < 8; q++) {
#pragma unroll
                for (int d = 0; d < 32; d++)
                    acc[q] = fmaf(zreg[d], cbs[q * 256 + dc + d], acc[q]);
            }
        }

#pragma unroll
        for (int q = 0; q < 8; q++) {
            float d2 = (zz + ccs[q]) - 2.0f * acc[q];
            if (d2 < best) { best = d2; bj = jc + q; }
        }
    }

    const float* crow = cb + (long)bj * 256;
    float* hqb = hq + (long)b * 256 * 256 + hw0;
    float l = 0.f;
    for (int d = 0; d < 256; d++) {
        float c = crow[d];
        hqb[d * 256 + p] = c;
        float diff = zs[d * POS + p] - c;
        l = fmaf(diff, diff, l);
    }
    lossp[b * 256 + hw0 + p] = l;
}

__global__ void loss_reduce_k(const float* __restrict__ lossp, float* __restrict__ out2)
{
    int tid = threadIdx.x;
    double s = 0.0;
    for (int i = tid; i < 32768; i += 1024) s += (double)lossp[i];
    __shared__ double sh[1024];
    sh[tid] = s;
    __syncthreads();
    for (int ofs = 512; ofs > 0; ofs >>= 1) {
        if (tid < ofs) sh[tid] += sh[tid + ofs];
        __syncthreads();
    }
    if (tid == 0) {
        float m = (float)(sh[0] / 32768.0);
        out2[0] = m;
        out2[1] = m;
    }
}

// ---------------------------------------------------------------------------
static inline int gridFor(int total, int block) { return (total + block - 1) / block; }

extern "C" void kernel_launch(void* const* d_in, const int* in_sizes, int n_in,
                              void* d_out, int out_size)
{
    const float* x        = (const float*)d_in[0];
    const float* codebook = (const float*)d_in[1];
    const float* e_w1 = (const float*)d_in[2];  const float* e_b1 = (const float*)d_in[3];
    const float* e_g1 = (const float*)d_in[4];  const float* e_be1 = (const float*)d_in[5];
    const float* e_w2 = (const float*)d_in[6];  const float* e_b2 = (const float*)d_in[7];
    const float* e_g2 = (const float*)d_in[8];  const float* e_be2 = (const float*)d_in[9];
    const float* e_w3 = (const float*)d_in[10]; const float* e_b3 = (const float*)d_in[11];
    const float* e_g3 = (const float*)d_in[12]; const float* e_be3 = (const float*)d_in[13];
    const float* e_w4 = (const float*)d_in[14]; const float* e_b4 = (const float*)d_in[15];
    const float* d_w1 = (const float*)d_in[16]; const float* d_b1 = (const float*)d_in[17];
    const float* d_g1 = (const float*)d_in[18]; const float* d_be1 = (const float*)d_in[19];
    const float* d_w2 = (const float*)d_in[20]; const float* d_b2 = (const float*)d_in[21];
    const float* d_g2 = (const float*)d_in[22]; const float* d_be2 = (const float*)d_in[23];
    const float* d_w3 = (const float*)d_in[24]; const float* d_b3 = (const float*)d_in[25];
    const float* d_g3 = (const float*)d_in[26]; const float* d_be3 = (const float*)d_in[27];
    const float* d_w4 = (const float*)d_in[28]; const float* d_b4 = (const float*)d_in[29];

    float* out = (float*)d_out;

    float *a1, *a2, *a3, *h4, *hq, *b1, *b2, *b3, *scale, *shift, *lossp, *cc;
    float *wt2, *wt3;
    u16 *b1h, *b1l, *b2h, *b2l, *wbh, *wbl, *w2bh, *w2bl;
    cudaGetSymbolAddress((void**)&a1, g_a1);
    cudaGetSymbolAddress((void**)&a2, g_a2);
    cudaGetSymbolAddress((void**)&a3, g_a3);
    cudaGetSymbolAddress((void**)&h4, g_h4);
    cudaGetSymbolAddress((void**)&hq, g_hq);
    cudaGetSymbolAddress((void**)&b1, g_d1);
    cudaGetSymbolAddress((void**)&b2, g_d2);
    cudaGetSymbolAddress((void**)&b3, g_d3);
    cudaGetSymbolAddress((void**)&scale, g_scale);
    cudaGetSymbolAddress((void**)&shift, g_shift);
    cudaGetSymbolAddress((void**)&lossp, g_lossp);
    cudaGetSymbolAddress((void**)&cc, g_cc);
    cudaGetSymbolAddress((void**)&wt2, g_wt2);
    cudaGetSymbolAddress((void**)&wt3, g_wt3);
    cudaGetSymbolAddress((void**)&b1h, g_b1h);
    cudaGetSymbolAddress((void**)&b1l, g_b1l);
    cudaGetSymbolAddress((void**)&b2h, g_b2h);
    cudaGetSymbolAddress((void**)&b2l, g_b2l);
    cudaGetSymbolAddress((void**)&wbh, g_wbh);
    cudaGetSymbolAddress((void**)&wbl, g_wbl);
    cudaGetSymbolAddress((void**)&w2bh, g_w2bh);
    cudaGetSymbolAddress((void**)&w2bl, g_w2bl);

    const int N = 128;

    const int SM_C2 = 2 * (4 * 18 * 66 + 4 * 16 * 64) * 4;
    const int SM_C3 = 2 * (4 * 18 * 34 + 4 * 16 * 64) * 4;
    const int SM_CL = 2 * (8 * 10 * 66) * 4;
    cudaFuncSetAttribute(convf3_k<32, 8, 4>, cudaFuncAttributeMaxDynamicSharedMemorySize, SM_C2);
    cudaFuncSetAttribute(convf3_k<16, 8, 4>, cudaFuncAttributeMaxDynamicSharedMemorySize, SM_C3);
    cudaFuncSetAttribute(convlast2_k, cudaFuncAttributeMaxDynamicSharedMemorySize, SM_CL);

    // weight preps
    wtr_fwd_k<<<gridFor(64 * 128 * 16, 256), 256>>>(e_w2, wt2, 64, 128);
    wtr_fwd_k<<<gridFor(128 * 192 * 16, 256), 256>>>(e_w3, wt3, 128, 192);
    wsplit3n_k<<<gridFor(4 * 8 * 16 * 4 * 64, 256), 256>>>(d_w3, wbh, wbl);
    wsplit2n_k<<<gridFor(4 * 12 * 16 * 4 * 128, 256), 256>>>(d_w2, w2bh, w2bl);

    // ---- encoder ----
    convf1_k<<<dim3(16, N), 256>>>(x, e_w1, e_b1, a1);
    bn_stats_k<<<64, 1024>>>(a1, e_g1, e_be1, scale, shift, 64, N, 4096);
    bn_apply4_k<<<gridFor(N * 64 * 1024, 256), 256>>>((float4*)a1, scale, shift, 64, 10,
                                                      N * 64 * 1024);

    convf3_k<32, 8, 4><<<dim3(4 * 2, N), 256, SM_C2>>>(a1, wt2, e_b2, a2, 64, 128, 4);
    bn_stats_k<<<128, 1024>>>(a2, e_g2, e_be2, scale, shift, 128, N, 1024);
    bn_apply4_k<<<gridFor(N * 128 * 256, 256), 256>>>((float4*)a2, scale, shift, 128, 8,
                                                      N * 128 * 256);

    convf3_k<16, 8, 4><<<dim3(2 * 3, N), 256, SM_C3>>>(a2, wt3, e_b3, a3, 128, 192, 2);
    bn_stats_k<<<192, 1024>>>(a3, e_g3, e_be3, scale, shift, 192, N, 256);
    bn_apply4_k<<<gridFor(N * 192 * 64, 256), 256>>>((float4*)a3, scale, shift, 192, 6,
                                                     N * 192 * 64);

    gemm1x1_k<32, false><<<dim3(2 * 4, N), 256>>>(a3, e_w4, e_b4, h4, 192, 256, 256, 2);

    // ---- vector quantization ----
    cc_k<<<1, 256>>>(codebook, cc);
    vq_exact_k<<<512, 64>>>(h4, codebook, cc, hq, lossp);
    loss_reduce_k<<<1, 1024>>>(lossp, out + (out_size - 2));

    // ---- decoder ----
    gemm1x1_k<32, true><<<dim3(2 * 3, N), 256>>>(hq, d_w1, d_b1, b1, 256, 256, 192, 2);
    bn_stats_k<<<192, 1024>>>(b1, d_g1, d_be1, scale, shift, 192, N, 256);
    bn_apply_split_k<<<gridFor(N * 192 * 128, 256), 256>>>((const float2*)b1, scale, shift,
                                                           (u32*)b1h, (u32*)b1l,
                                                           192, 8, N * 192 * 128);

    convt_mma2_k<<<dim3(2, N, 4), 256>>>(b1h, b1l, w2bh, w2bl, d_b2, b2);
    bn_stats_k<<<128, 1024>>>(b2, d_g2, d_be2, scale, shift, 128, N, 1024);
    bn_apply_split_k<<<gridFor(N * 128 * 512, 256), 256>>>((const float2*)b2, scale, shift,
                                                           (u32*)b2h, (u32*)b2l,
                                                           128, 10, N * 128 * 512);

    convt_mma_k<<<dim3(8, N, 4), 256>>>(b2h, b2l, wbh, wbl, d_b3, b3);
    bn_stats_k<<<64, 1024>>>(b3, d_g3, d_be3, scale, shift, 64, N, 4096);
    bn_apply4_k<<<gridFor(N * 64 * 1024, 256), 256>>>((float4*)b3, scale, shift, 64, 10,
                                                      N * 64 * 1024);

    convlast2_k<<<dim3(8, N), 256, SM_CL>>>(b3, d_w4, d_b4, out);
}

// round 16
// speedup vs baseline: 1.1233x; 1.1233x over previous
#include <cuda_runtime.h>
#include <cuda_bf16.h>
#include <math_constants.h>

typedef unsigned long long u64;
typedef unsigned short u16;
typedef unsigned int u32;

__device__ __forceinline__ u64 pk(float lo, float hi) {
    u64 r;
    asm("mov.b64 %0, {%1, %2};" : "=l"(r) : "f"(lo), "f"(hi));
    return r;
}
__device__ __forceinline__ void upk(u64 v, float& lo, float& hi) {
    asm("mov.b64 {%0, %1}, %2;" : "=f"(lo), "=f"(hi) : "l"(v));
}
__device__ __forceinline__ void fma2(u64& d, u64 a, u64 b) {
    asm("fma.rn.f32x2 %0, %1, %2, %0;" : "+l"(d) : "l"(a), "l"(b));
}
__device__ __forceinline__ unsigned s2u(const void* p) {
    return (unsigned)__cvta_generic_to_shared(p);
}
__device__ __forceinline__ void cpa4(unsigned saddr, const float* g, bool v) {
    int sz = v ? 4 : 0;
    asm volatile("cp.async.ca.shared.global [%0], [%1], 4, %2;"
                 :: "r"(saddr), "l"(g), "r"(sz) : "memory");
}
__device__ __forceinline__ void cpa4u(unsigned saddr, const u16* g, bool v) {
    int sz = v ? 4 : 0;
    asm volatile("cp.async.ca.shared.global [%0], [%1], 4, %2;"
                 :: "r"(saddr), "l"(g), "r"(sz) : "memory");
}
__device__ __forceinline__ void cpa16(unsigned saddr, const void* g) {
    asm volatile("cp.async.cg.shared.global [%0], [%1], 16;"
                 :: "r"(saddr), "l"(g) : "memory");
}
#define CP_COMMIT() asm volatile("cp.async.commit_group;" ::: "memory")
#define CP_WAIT0()  asm volatile("cp.async.wait_group 0;" ::: "memory")

// warp-level bf16 MMA (sm_80+ baseline PTX)
__device__ __forceinline__ void mma16816(float* c, const u32* a, const u32* b) {
    asm volatile(
        "mma.sync.aligned.m16n8k16.row.col.f32.bf16.bf16.f32 "
        "{%0,%1,%2,%3}, {%4,%5,%6,%7}, {%8,%9}, {%0,%1,%2,%3};"
        : "+f"(c[0]), "+f"(c[1]), "+f"(c[2]), "+f"(c[3])
        : "r"(a[0]), "r"(a[1]), "r"(a[2]), "r"(a[3]), "r"(b[0]), "r"(b[1]));
}

// Scratch buffers
__device__ float g_a1[128 * 64 * 64 * 64];
__device__ float g_a2[128 * 128 * 32 * 32];
__device__ float g_a3[128 * 192 * 16 * 16];
__device__ float g_h4[128 * 256 * 16 * 16];
__device__ float g_hq[128 * 256 * 16 * 16];
__device__ float g_d1[128 * 192 * 16 * 16];
__device__ float g_d2[128 * 128 * 32 * 32];
__device__ float g_d3[128 * 64 * 64 * 64];
__device__ float g_scale[256];
__device__ float g_shift[256];
__device__ float g_lossp[32768];
__device__ float g_cc[256];
__device__ float g_wt2[64 * 16 * 128];
__device__ float g_wt3[128 * 16 * 192];
// bf16 hi/lo planes
__device__ u16 g_b1h[128 * 192 * 256];
__device__ u16 g_b1l[128 * 192 * 256];
__device__ u16 g_b2h[128 * 128 * 1024];
__device__ u16 g_b2l[128 * 128 * 1024];
// MMA weights
__device__ u16 g_wbh[4 * 8 * 4096];
__device__ u16 g_wbl[4 * 8 * 4096];
__device__ u16 g_w2bh[4 * 12 * 8192];
__device__ u16 g_w2bl[4 * 12 * 8192];

__global__ void wtr_fwd_k(const float* __restrict__ w, float* __restrict__ wt,
                          int Cin, int Cout)
{
    int i = blockIdx.x * 256 + threadIdx.x;
    int total = Cin * Cout * 16;
    if (i >= total) return;
    int oc = i % Cout; int r = i / Cout;
    int t = r & 15; int ic = r >> 4;
    wt[i] = w[((long)oc * Cin + ic) * 16 + t];
}

// d3 weights -> per (cls,chunk) [64 oc][64 k]
__global__ void wsplit3n_k(const float* __restrict__ w, u16* __restrict__ wbh,
                           u16* __restrict__ wbl)
{
    int i = blockIdx.x * 256 + threadIdx.x;
    if (i >= 4 * 8 * 16 * 4 * 64) return;
    int oc  = i & 63;
    int t   = (i >> 6) & 3;
    int icl = (i >> 8) & 15;
    int cc  = (i >> 12) & 7;
    int cls = i >> 15;
    int a = cls >> 1, b = cls & 1;
    int ic = cc * 16 + icl;
    float v = w[((long)ic * 64 + oc) * 16
                + (1 - a + 2 * (t >> 1)) * 4 + (1 - b + 2 * (t & 1))];
    __nv_bfloat16 h = __float2bfloat16(v);
    float hf = __bfloat162float(h);
    __nv_bfloat16 l = __float2bfloat16(v - hf);
    int idx = (cls * 8 + cc) * 4096 + oc * 64 + (icl * 4 + t);
    wbh[idx] = __bfloat16_as_ushort(h);
    wbl[idx] = __bfloat16_as_ushort(l);
}

// d2 weights -> per (cls,chunk12) [128 oc][64 k]
__global__ void wsplit2n_k(const float* __restrict__ w, u16* __restrict__ wbh,
                           u16* __restrict__ wbl)
{
    int i = blockIdx.x * 256 + threadIdx.x;
    if (i >= 4 * 12 * 16 * 4 * 128) return;
    int oc  = i & 127;
    int t   = (i >> 7) & 3;
    int icl = (i >> 9) & 15;
    int cc  = (i >> 13) % 12;
    int cls = i / (12 * 8192);
    int a = cls >> 1, b = cls & 1;
    int ic = cc * 16 + icl;
    float v = w[((long)ic * 128 + oc) * 16
                + (1 - a + 2 * (t >> 1)) * 4 + (1 - b + 2 * (t & 1))];
    __nv_bfloat16 h = __float2bfloat16(v);
    float hf = __bfloat162float(h);
    __nv_bfloat16 l = __float2bfloat16(v - hf);
    int idx = (cls * 12 + cc) * 8192 + oc * 64 + (icl * 4 + t);
    wbh[idx] = __bfloat16_as_ushort(h);
    wbl[idx] = __bfloat16_as_ushort(l);
}

// BN apply + ReLU + bf16 hi/lo split
__global__ void bn_apply_split_k(const float2* __restrict__ x,
                                 const float* __restrict__ scale,
                                 const float* __restrict__ shift,
                                 u32* __restrict__ hi, u32* __restrict__ lo,
                                 int C, int hwsh, int total2)
{
    int i = blockIdx.x * 256 + threadIdx.x;
    if (i >= total2) return;
    int c = ((i * 2) >> hwsh) % C;
    float s = scale[c], t = shift[c];
    float2 v = x[i];
    float v0 = fmaxf(fmaf(v.x, s, t), 0.f);
    float v1 = fmaxf(fmaf(v.y, s, t), 0.f);
    __nv_bfloat16 h0 = __float2bfloat16(v0);
    __nv_bfloat16 h1 = __float2bfloat16(v1);
    __nv_bfloat16 l0 = __float2bfloat16(v0 - __bfloat162float(h0));
    __nv_bfloat16 l1 = __float2bfloat16(v1 - __bfloat162float(h1));
    hi[i] = (u32)__bfloat16_as_ushort(h0) | ((u32)__bfloat16_as_ushort(h1) << 16);
    lo[i] = (u32)__bfloat16_as_ushort(l0) | ((u32)__bfloat16_as_ushort(l1) << 16);
}

// ---------------------------------------------------------------------------
// d3 via warp mma bf16-split, cp.async double-buffered staging.
// Per buffer (u32): sBh 2304 | sBl 2304 | sRH 1280 | sRL 1280 = 7168.
// ---------------------------------------------------------------------------
__global__ void __launch_bounds__(256)
convt_mma_k(const u16* __restrict__ b2h, const u16* __restrict__ b2l,
            const u16* __restrict__ wbh, const u16* __restrict__ wbl,
            const float* __restrict__ bias, float* __restrict__ out)
{
    extern __shared__ u32 smd3[];
    constexpr int BUF = 7168;

    int tid = threadIdx.x;
    int wrp = tid >> 5, lane = tid & 31;
    int g = lane >> 2, tq = lane & 3;
    int pxt = blockIdx.x;
    int n   = blockIdx.y;
    int cls = blockIdx.z;
    int a = cls >> 1, b = cls & 1;
    int s0 = pxt * 4;
    int rb = wrp * 16;

    float acc[8][4];
#pragma unroll
    for (int nt = 0; nt < 8; nt++)
#pragma unroll
        for (int r = 0; r < 4; r++) acc[nt][r] = 0.f;

    long nbase = (long)n << 17;

    auto afrag = [&](const u16* raw, int pos, int k) -> u32 {
        int sr = pos >> 5, c = pos & 31;
        int icl = k >> 2, t = k & 3;
        int ty = t >> 1;
        const u16* rowp = raw + (icl * 5 + (sr + 1 - ty)) * 32;
        int xa = c + b;
        u32 v0 = (xa < 32) ? (u32)rowp[xa] : 0u;
        u32 v1 = (xa >= 1) ? (u32)rowp[xa - 1] : 0u;
        return v0 | (v1 << 16);
    };

    auto stage = [&](int cc, u32* buf) {
        const u16* gh = wbh + (cls * 8 + cc) * 4096;
        const u16* gl = wbl + (cls * 8 + cc) * 4096;
        unsigned bh_s = s2u(buf);
        unsigned bl_s = s2u(buf + 2304);
        for (int i = tid; i < 512; i += 256) {
            int oc = i >> 3, seg = i & 7;
            cpa16(bh_s + (oc * 36 + seg * 4) * 4, gh + oc * 64 + seg * 8);
            cpa16(bl_s + (oc * 36 + seg * 4) * 4, gl + oc * 64 + seg * 8);
        }
        unsigned rh_s = s2u(buf + 4608);
        unsigned rl_s = s2u(buf + 5888);
        for (int i = tid; i < 1280; i += 256) {
            int x2 = i & 15;
            int j = (i >> 4) % 5;
            int icl = i / 80;
            int y = s0 + a - 1 + j;
            bool v = (unsigned)y < 32u;
            long off = nbase + (v ? (((long)(cc * 16 + icl) << 10) + y * 32 + 2 * x2) : 0);
            cpa4u(rh_s + i * 4, b2h + off, v);
            cpa4u(rl_s + i * 4, b2l + off, v);
        }
    };

    auto compute = [&](const u32* buf) {
        const u32* sBh = buf;
        const u32* sBl = buf + 2304;
        const u16* rawh = (const u16*)(buf + 4608);
        const u16* rawl = (const u16*)(buf + 5888);

        u32 AH[4][4], AL[4][4];
#pragma unroll
        for (int ks = 0; ks < 4; ks++) {
            int k0 = ks * 16 + 2 * tq;
            AH[ks][0] = afrag(rawh, rb + g, k0);
            AH[ks][1] = afrag(rawh, rb + g + 8, k0);
            AH[ks][2] = afrag(rawh, rb + g, k0 + 8);
            AH[ks][3] = afrag(rawh, rb + g + 8, k0 + 8);
            AL[ks][0] = afrag(rawl, rb + g, k0);
            AL[ks][1] = afrag(rawl, rb + g + 8, k0);
            AL[ks][2] = afrag(rawl, rb + g, k0 + 8);
            AL[ks][3] = afrag(rawl, rb + g + 8, k0 + 8);
        }
#pragma unroll
        for (int nt = 0; nt < 8; nt++) {
            int oc = nt * 8 + g;
#pragma unroll
            for (int ks = 0; ks < 4; ks++) {
                u32 bh[2], bl[2];
                bh[0] = sBh[oc * 36 + ks * 8 + tq];
                bh[1] = sBh[oc * 36 + ks * 8 + tq + 4];
                bl[0] = sBl[oc * 36 + ks * 8 + tq];
                bl[1] = sBl[oc * 36 + ks * 8 + tq + 4];
                mma16816(acc[nt], AH[ks], bh);
                mma16816(acc[nt], AH[ks], bl);
                mma16816(acc[nt], AL[ks], bh);
            }
        }
    };

    u32* buf0 = smd3;
    u32* buf1 = smd3 + BUF;
    stage(0, buf0);
    CP_COMMIT();
    CP_WAIT0();
    __syncthreads();
    for (int cc = 0; cc < 8; cc++) {
        u32* cbuf = (cc & 1) ? buf1 : buf0;
        u32* nbuf = (cc & 1) ? buf0 : buf1;
        if (cc + 1 < 8) { stage(cc + 1, nbuf); CP_COMMIT(); }
        compute(cbuf);
        if (cc + 1 < 8) { CP_WAIT0(); __syncthreads(); }
    }

#pragma unroll
    for (int nt = 0; nt < 8; nt++) {
        int oc0 = nt * 8 + 2 * tq;
        float b0 = bias[oc0], b1 = bias[oc0 + 1];
#pragma unroll
        for (int rh = 0; rh < 2; rh++) {
            int pos = rb + g + rh * 8;
            int sr = pos >> 5, c = pos & 31;
            int oy = 2 * (s0 + sr) + a;
            int ox = 2 * c + b;
            long ob = (((long)n * 64 + oc0) * 64 + oy) * 64 + ox;
            out[ob] = acc[nt][rh * 2] + b0;
            out[ob + 4096] = acc[nt][rh * 2 + 1] + b1;
        }
    }
}

// ---------------------------------------------------------------------------
// d2 via warp mma bf16-split, cp.async double-buffered staging.
// Per buffer (u32): sBh 4608 | sBl 4608 | sRH 1152 | sRL 1152 = 11520.
// ---------------------------------------------------------------------------
__global__ void __launch_bounds__(256)
convt_mma2_k(const u16* __restrict__ b1h, const u16* __restrict__ b1l,
             const u16* __restrict__ wbh, const u16* __restrict__ wbl,
             const float* __restrict__ bias, float* __restrict__ out)
{
    extern __shared__ u32 smd2[];
    constexpr int BUF = 11520;

    int tid = threadIdx.x;
    int wrp = tid >> 5, lane = tid & 31;
    int g = lane >> 2, tq = lane & 3;
    int pxt = blockIdx.x;
    int n   = blockIdx.y;
    int cls = blockIdx.z;
    int a = cls >> 1, b = cls & 1;
    int s0 = pxt * 8;
    int rb = wrp * 16;

    float acc[16][4];
#pragma unroll
    for (int nt = 0; nt < 16; nt++)
#pragma unroll
        for (int r = 0; r < 4; r++) acc[nt][r] = 0.f;

    long nbase = (long)n * 192 * 256;

    auto afrag = [&](const u16* raw, int pos, int k) -> u32 {
        int sr = pos >> 4, c = pos & 15;
        int icl = k >> 2, t = k & 3;
        int ty = t >> 1;
        const u16* rowp = raw + (icl * 9 + (sr + 1 - ty)) * 16;
        int xa = c + b;
        u32 v0 = (xa < 16) ? (u32)rowp[xa] : 0u;
        u32 v1 = (xa >= 1) ? (u32)rowp[xa - 1] : 0u;
        return v0 | (v1 << 16);
    };

    auto stage = [&](int cc, u32* buf) {
        const u16* gh = wbh + (cls * 12 + cc) * 8192;
        const u16* gl = wbl + (cls * 12 + cc) * 8192;
        unsigned bh_s = s2u(buf);
        unsigned bl_s = s2u(buf + 4608);
        for (int i = tid; i < 1024; i += 256) {
            int oc = i >> 3, seg = i & 7;
            cpa16(bh_s + (oc * 36 + seg * 4) * 4, gh + oc * 64 + seg * 8);
            cpa16(bl_s + (oc * 36 + seg * 4) * 4, gl + oc * 64 + seg * 8);
        }
        unsigned rh_s = s2u(buf + 9216);
        unsigned rl_s = s2u(buf + 10368);
        for (int i = tid; i < 1152; i += 256) {
            int x2 = i & 7;
            int j = (i >> 3) % 9;
            int icl = i / 72;
            int y = s0 + a - 1 + j;
            bool v = (unsigned)y < 16u;
            long off = nbase + (v ? ((long)(cc * 16 + icl) * 256 + y * 16 + 2 * x2) : 0);
            cpa4u(rh_s + i * 4, b1h + off, v);
            cpa4u(rl_s + i * 4, b1l + off, v);
        }
    };

    auto compute = [&](const u32* buf) {
        const u32* sBh = buf;
        const u32* sBl = buf + 4608;
        const u16* rawh = (const u16*)(buf + 9216);
        const u16* rawl = (const u16*)(buf + 10368);

        u32 AH[4][4], AL[4][4];
#pragma unroll
        for (int ks = 0; ks < 4; ks++) {
            int k0 = ks * 16 + 2 * tq;
            AH[ks][0] = afrag(rawh, rb + g, k0);
            AH[ks][1] = afrag(rawh, rb + g + 8, k0);
            AH[ks][2] = afrag(rawh, rb + g, k0 + 8);
            AH[ks][3] = afrag(rawh, rb + g + 8, k0 + 8);
            AL[ks][0] = afrag(rawl, rb + g, k0);
            AL[ks][1] = afrag(rawl, rb + g + 8, k0);
            AL[ks][2] = afrag(rawl, rb + g, k0 + 8);
            AL[ks][3] = afrag(rawl, rb + g + 8, k0 + 8);
        }
#pragma unroll
        for (int nt = 0; nt < 16; nt++) {
            int oc = nt * 8 + g;
#pragma unroll
            for (int ks = 0; ks < 4; ks++) {
                u32 bh[2], bl[2];
                bh[0] = sBh[oc * 36 + ks * 8 + tq];
                bh[1] = sBh[oc * 36 + ks * 8 + tq + 4];
                bl[0] = sBl[oc * 36 + ks * 8 + tq];
                bl[1] = sBl[oc * 36 + ks * 8 + tq + 4];
                mma16816(acc[nt], AH[ks], bh);
                mma16816(acc[nt], AH[ks], bl);
                mma16816(acc[nt], AL[ks], bh);
            }
        }
    };

    u32* buf0 = smd2;
    u32* buf1 = smd2 + BUF;
    stage(0, buf0);
    CP_COMMIT();
    CP_WAIT0();
    __syncthreads();
    for (int cc = 0; cc < 12; cc++) {
        u32* cbuf = (cc & 1) ? buf1 : buf0;
        u32* nbuf = (cc & 1) ? buf0 : buf1;
        if (cc + 1 < 12) { stage(cc + 1, nbuf); CP_COMMIT(); }
        compute(cbuf);
        if (cc + 1 < 12) { CP_WAIT0(); __syncthreads(); }
    }

#pragma unroll
    for (int nt = 0; nt < 16; nt++) {
        int oc0 = nt * 8 + 2 * tq;
        float b0 = bias[oc0], b1 = bias[oc0 + 1];
#pragma unroll
        for (int rh = 0; rh < 2; rh++) {
            int pos = rb + g + rh * 8;
            int sr = pos >> 4, c = pos & 15;
            int oy = 2 * (s0 + sr) + a;
            int ox = 2 * c + b;
            long ob = (((long)n * 128 + oc0) * 32 + oy) * 32 + ox;
            out[ob] = acc[nt][rh * 2] + b0;
            out[ob + 1024] = acc[nt][rh * 2 + 1] + b1;
        }
    }
}

// ---------------------------------------------------------------------------
// k4 s2 p1 forward conv, oc-packed fma2, cp.async (round 7, unchanged).
// ---------------------------------------------------------------------------
template <int COLS, int RB, int ICT>
__global__ void __launch_bounds__(256, 2)
convf3_k(const float* __restrict__ in, const float* __restrict__ wt,
         const float* __restrict__ bias, float* __restrict__ out,
         int Cin, int Cout, int npx)
{
    constexpr int HL = 32 / COLS;
    constexpr int RT = RB / (2 * HL);
    constexpr int SROWS = 2 * RB + 2;
    constexpr int SLOTW = 2 * COLS + 2;
    constexpr int SU = ICT * SROWS * SLOTW;
    constexpr int SW = ICT * 16 * 64;
    constexpr int BUF = SU + SW;
    extern __shared__ float smdyn[];

    const int Win = 2 * COLS, Hin = 2 * COLS;

    int n   = blockIdx.y;
    int pxt = blockIdx.x % npx;
    int oct = blockIdx.x / npx;
    int tid = threadIdx.x;
    int wrp = tid >> 5, lane = tid & 31;
    int og = wrp >> 1, rg = wrp & 1;
    int c  = lane % COLS, h = lane / COLS;
    int oy0 = pxt * RB;
    int ocb = oct * 64 + og * 16;
    int rl0 = rg * (RB / 2) + h * RT;

    u64 acc[8][RT];
#pragma unroll
    for (int j = 0; j < 8; j++) {
        u64 b2 = pk(bias[ocb + 2 * j], bias[ocb + 2 * j + 1]);
#pragma unroll
        for (int i = 0; i < RT; i++) acc[j][i] = b2;
    }

    auto stage = [&](int ic0, float* buf) {
        unsigned su_s = s2u(buf);
        unsigned sw_s = s2u(buf + SU);
        const float* ibase = in + ((long)n * Cin + ic0) * (long)(Hin * Win);
        for (int i = tid; i < SU; i += 256) {
            int s = i % SLOTW;
            int j = (i / SLOTW) % SROWS;
            int icl = i / (SLOTW * SROWS);
            int x = s - 1;
            int iy = 2 * oy0 - 1 + j;
            bool vld = (unsigned)x < (unsigned)Win && (unsigned)iy < (unsigned)Hin;
            const float* gp = vld ? ibase + (long)icl * (Hin * Win) + iy * Win + x
                                  : ibase;
            cpa4(su_s + i * 4, gp, vld);
        }
        for (int i4 = tid; i4 < SW / 4; i4 += 256) {
            int i = i4 * 4;
            int oc = i & 63;
            int row = i >> 6;
            const float* gp = wt + ((long)(ic0 * 16 + row)) * Cout + oct * 64 + oc;
            cpa16(sw_s + i * 4, gp);
        }
    };

    auto compute = [&](const float* buf) {
        const float* su = buf;
        const float* swp = buf + SU;
#pragma unroll 1
        for (int icl = 0; icl < ICT; icl++) {
#pragma unroll
            for (int ky = 0; ky < 4; ky++) {
                u64 qd[RT][4];
#pragma unroll
                for (int i = 0; i < RT; i++) {
                    const float* row = su + (icl * SROWS + 2 * (rl0 + i) + ky) * SLOTW + 2 * c;
                    float2 f01 = *(const float2*)(row);
                    float2 f23 = *(const float2*)(row + 2);
                    qd[i][0] = pk(f01.x, f01.x);
                    qd[i][1] = pk(f01.y, f01.y);
                    qd[i][2] = pk(f23.x, f23.x);
                    qd[i][3] = pk(f23.y, f23.y);
                }
#pragma unroll
                for (int kx = 0; kx < 4; kx++) {
                    const ulonglong2* wp =
                        (const ulonglong2*)(swp + (icl * 16 + ky * 4 + kx) * 64 + og * 16);
                    ulonglong2 w01 = wp[0];
                    ulonglong2 w23 = wp[1];
                    ulonglong2 w45 = wp[2];
                    ulonglong2 w67 = wp[3];
#pragma unroll
                    for (int i = 0; i < RT; i++) {
                        fma2(acc[0][i], qd[i][kx], w01.x);
                        fma2(acc[1][i], qd[i][kx], w01.y);
                        fma2(acc[2][i], qd[i][kx], w23.x);
                        fma2(acc[3][i], qd[i][kx], w23.y);
                        fma2(acc[4][i], qd[i][kx], w45.x);
                        fma2(acc[5][i], qd[i][kx], w45.y);
                        fma2(acc[6][i], qd[i][kx], w67.x);
                        fma2(acc[7][i], qd[i][kx], w67.y);
                    }
                }
            }
        }
    };

    float* buf0 = smdyn;
    float* buf1 = smdyn + BUF;
    stage(0, buf0);
    CP_COMMIT();
    CP_WAIT0();
    __syncthreads();
    int nch = Cin / ICT;
    for (int ch = 0; ch < nch; ch++) {
        float* cbuf = (ch & 1) ? buf1 : buf0;
        float* nbuf = (ch & 1) ? buf0 : buf1;
        if (ch + 1 < nch) { stage((ch + 1) * ICT, nbuf); CP_COMMIT(); }
        compute(cbuf);
        if (ch + 1 < nch) { CP_WAIT0(); __syncthreads(); }
    }

#pragma unroll
    for (int j = 0; j < 8; j++) {
#pragma unroll
        for (int i = 0; i < RT; i++) {
            float lo, hi;
            upk(acc[j][i], lo, hi);
            long o0 = ((long)n * Cout + ocb + 2 * j) * (COLS * COLS)
                    + (oy0 + rl0 + i) * COLS + c;
            out[o0] = lo;
            out[o0 + COLS * COLS] = hi;
        }
    }
}

// ---------------------------------------------------------------------------
// conv1 (3->64 k3 s1 p1), column-pair fma2 (round 15, bit-exact).
// ---------------------------------------------------------------------------
__global__ void __launch_bounds__(256)
convf1_k(const float* __restrict__ in, const float* __restrict__ w,
         const float* __restrict__ bias, float* __restrict__ out)
{
    __shared__ u64 pu[3 * 6 * 34];
    __shared__ u64 sw[3 * 64 * 12];

    int n = blockIdx.y;
    int rt0 = blockIdx.x * 4;
    int tid = threadIdx.x;
    int wrp = tid >> 5, lane = tid & 31;
    int ocb = wrp * 8;

    for (int i = tid; i < 3 * 64 * 12; i += 256) sw[i] = 0ull;
    __syncthreads();
    for (int i = tid; i < 3 * 64 * 9; i += 256) {
        int kk = i % 9; int oc = (i / 9) % 64; int ic = i / (9 * 64);
        float v = w[((long)oc * 3 + ic) * 9 + kk];
        sw[(ic * 64 + oc) * 12 + (kk / 3) * 4 + kk % 3] = pk(v, v);
    }
    const float* ib = in + (long)n * 3 * 4096;
    for (int i = tid; i < 3 * 6 * 34; i += 256) {
        int t = i % 34; int r = (i / 34) % 6; int ic = i / (34 * 6);
        int gy = rt0 - 1 + r;
        bool yv = (unsigned)gy < 64u;
        float lo = (yv && t >= 1) ? ib[ic * 4096 + gy * 64 + t - 1] : 0.f;
        float hi = (yv && t <= 32) ? ib[ic * 4096 + gy * 64 + t + 31] : 0.f;
        pu[i] = pk(lo, hi);
    }
    __syncthreads();

    u64 acc[8][4];
#pragma unroll
    for (int o = 0; o < 8; o++) {
        float b = bias[ocb + o];
#pragma unroll
        for (int r = 0; r < 4; r++) acc[o][r] = pk(b, b);
    }

#pragma unroll
    for (int ic = 0; ic < 3; ic++) {
#pragma unroll
        for (int ky = 0; ky < 3; ky++) {
            u64 q[4][3];
#pragma unroll
            for (int r = 0; r < 4; r++) {
                const u64* rowp = pu + (ic * 6 + r + ky) * 34 + lane;
                q[r][0] = rowp[0];
                q[r][1] = rowp[1];
                q[r][2] = rowp[2];
            }
#pragma unroll
            for (int o = 0; o < 8; o++) {
                const u64* wb = sw + (ic * 64 + ocb + o) * 12 + ky * 4;
                ulonglong2 w01 = ((const ulonglong2*)wb)[0];
                u64 w2 = wb[2];
#pragma unroll
                for (int r = 0; r < 4; r++) {
                    fma2(acc[o][r], q[r][0], w01.x);
                    fma2(acc[o][r], q[r][1], w01.y);
                    fma2(acc[o][r], q[r][2], w2);
                }
            }
        }
    }

#pragma unroll
    for (int o = 0; o < 8; o++) {
#pragma unroll
        for (int r = 0; r < 4; r++) {
            float lo, hi;
            upk(acc[o][r], lo, hi);
            long ob = (((long)n * 64 + ocb + o) * 64 + rt0 + r) * 64 + lane;
            out[ob] = lo;
            out[ob + 32] = hi;
        }
    }
}

// ---------------------------------------------------------------------------
// Final conv 64 -> 3 (round 15, bit-exact).
// ---------------------------------------------------------------------------
__global__ void __launch_bounds__(256, 3)
convlast2_k(const float* __restrict__ in, const float* __restrict__ w,
            const float* __restrict__ bias, float* __restrict__ out)
{
    constexpr int ICT = 8;
    constexpr int SROWS = 10;
    constexpr int SLOTW = 66;
    constexpr int SU = ICT * SROWS * SLOTW;
    extern __shared__ float smdyn[];
    __shared__ u64 ws2[64 * 3 * 12];

    int n  = blockIdx.y;
    int r0 = blockIdx.x * 8;
    int tid = threadIdx.x;
    int x  = tid & 63;
    int rq = tid >> 6;

    for (int i = tid; i < 64 * 3 * 12; i += 256) ws2[i] = 0ull;
    __syncthreads();
    for (int i = tid; i < 64 * 3 * 9; i += 256) {
        int kk = i % 9; int t = i / 9; int oc = t % 3; int ic = t / 3;
        float v = w[((long)oc * 64 + ic) * 9 + kk];
        ws2[((ic * 3 + oc) * 3 + kk / 3) * 4 + kk % 3] = pk(v, v);
    }

    u64 acc[3];
#pragma unroll
    for (int o = 0; o < 3; o++) {
        float b = bias[o];
        acc[o] = pk(b, b);
    }

    const float* ib = in + (long)n * 64 * 4096;

    auto stage = [&](int ic0, float* buf) {
        unsigned su_s = s2u(buf);
        for (int i = tid; i < SU; i += 256) {
            int s = i % SLOTW;
            int j = (i / SLOTW) % SROWS;
            int icl = i / (SLOTW * SROWS);
            int xx = s - 1;
            int iy = r0 - 1 + j;
            bool vld = (unsigned)xx < 64u && (unsigned)iy < 64u;
            const float* gp = vld ? ib + (long)(ic0 + icl) * 4096 + iy * 64 + xx : ib;
            cpa4(su_s + i * 4, gp, vld);
        }
    };

    auto compute = [&](const float* su, int ic0) {
#pragma unroll 1
        for (int icl = 0; icl < ICT; icl++) {
            int ic = ic0 + icl;
#pragma unroll
            for (int ky = 0; ky < 3; ky++) {
                const float* rl = su + (icl * SROWS + rq + ky) * SLOTW + x;
                const float* rh = su + (icl * SROWS + rq + 4 + ky) * SLOTW + x;
                float a0 = rl[0], a1 = rl[1], a2 = rl[2];
                float b0 = rh[0], b1 = rh[1], b2 = rh[2];
                u64 q0 = pk(a0, b0), q1 = pk(a1, b1), q2 = pk(a2, b2);
#pragma unroll
                for (int o = 0; o < 3; o++) {
                    const u64* wb = ws2 + ((ic * 3 + o) * 3 + ky) * 4;
                    ulonglong2 w01 = ((const ulonglong2*)wb)[0];
                    u64 w2 = wb[2];
                    fma2(acc[o], q0, w01.x);
                    fma2(acc[o], q1, w01.y);
                    fma2(acc[o], q2, w2);
                }
            }
        }
    };

    float* buf0 = smdyn;
    float* buf1 = smdyn + SU;
    stage(0, buf0);
    CP_COMMIT();
    CP_WAIT0();
    __syncthreads();
    const int nch = 64 / ICT;
    for (int ch = 0; ch < nch; ch++) {
        float* cbuf = (ch & 1) ? buf1 : buf0;
        float* nbuf = (ch & 1) ? buf0 : buf1;
        if (ch + 1 < nch) { stage((ch + 1) * ICT, nbuf); CP_COMMIT(); }
        compute(cbuf, ch * ICT);
        if (ch + 1 < nch) { CP_WAIT0(); __syncthreads(); }
    }

#pragma unroll
    for (int o = 0; o < 3; o++) {
        float lo, hi;
        upk(acc[o], lo, hi);
        long ob = ((long)n * 3 + o) * 4096 + (r0 + rq) * 64 + x;
        out[ob] = lo;
        out[ob + 4 * 64] = hi;
    }
}

// ---------------------------------------------------------------------------
// 1x1 conv / convT as GEMM (round-7 version).
// ---------------------------------------------------------------------------
template <int ICT, bool TRANS>
__global__ void __launch_bounds__(256)
gemm1x1_k(const float* __restrict__ in, const float* __restrict__ w,
          const float* __restrict__ bias, float* __restrict__ out,
          int Cin, int HW, int Cout, int npx)
{
    __shared__ u64 ws2[ICT * 64];
    int n = blockIdx.y;
    int pxt = blockIdx.x % npx, oct = blockIdx.x / npx;
    int tid = threadIdx.x;
    int g = tid >> 5, lane = tid & 31;
    int hw0 = pxt * 128 + lane * 4;
    int ocb = oct * 64 + g * 8;

    u64 acc[8][2];
#pragma unroll
    for (int o = 0; o < 8; o++) {
        float b = bias[ocb + o];
        acc[o][0] = pk(b, b);
        acc[o][1] = pk(b, b);
    }

    long inb = (long)n * Cin * HW + hw0;

    for (int ic0 = 0; ic0 < Cin; ic0 += ICT) {
        __syncthreads();
        for (int i = tid; i < ICT * 64; i += 256) {
            int oc = i & 63, ic = i >> 6;
            float v = TRANS ? w[(long)(ic0 + ic) * Cout + oct * 64 + oc]
                            : w[(long)(oct * 64 + oc) * Cin + ic0 + ic];
            ws2[i] = pk(v, v);
        }
        __syncthreads();

        for (int ic = 0; ic < ICT; ic++) {
            float4 v = *(const float4*)(in + inb + (long)(ic0 + ic) * HW);
            u64 U0 = pk(v.x, v.y), U1 = pk(v.z, v.w);
            const ulonglong2* wp = (const ulonglong2*)(ws2 + ic * 64 + g * 8);
#pragma unroll
            for (int k = 0; k < 4; k++) {
                ulonglong2 ww = wp[k];
                fma2(acc[2 * k][0], U0, ww.x);     fma2(acc[2 * k][1], U1, ww.x);
                fma2(acc[2 * k + 1][0], U0, ww.y); fma2(acc[2 * k + 1][1], U1, ww.y);
            }
        }
    }

    long ob = ((long)n * Cout + ocb) * HW + hw0;
#pragma unroll
    for (int o = 0; o < 8; o++) {
        float4 v;
        upk(acc[o][0], v.x, v.y);
        upk(acc[o][1], v.z, v.w);
        *(float4*)(out + ob + (long)o * HW) = v;
    }
}

// ---------------------------------------------------------------------------
// BatchNorm stats (bit-identical scale/shift).
// ---------------------------------------------------------------------------
__global__ void bn_stats_k(const float* __restrict__ x, const float* __restrict__ g,
                           const float* __restrict__ be, float* __restrict__ scale,
                           float* __restrict__ shift, int C, int N, int HW)
{
    int c = blockIdx.x;
    int tid = threadIdx.x;
    float s = 0.f, ss = 0.f;
    for (int n = 0; n < N; n++) {
        const float* p = x + ((long)(n * C + c)) * HW;
        for (int r = tid; r < HW; r += blockDim.x) {
            float v = p[r];
            s += v; ss += v * v;
        }
    }
    __shared__ float sh1[1024];
    __shared__ float sh2[1024];
    sh1[tid] = s; sh2[tid] = ss;
    __syncthreads();
    for (int ofs = blockDim.x >> 1; ofs > 0; ofs >>= 1) {
        if (tid < ofs) { sh1[tid] += sh1[tid + ofs]; sh2[tid] += sh2[tid + ofs]; }
        __syncthreads();
    }
    if (tid == 0) {
        float cnt = (float)N * (float)HW;
        float m = sh1[0] / cnt;
        float var = sh2[0] / cnt - m * m;
        float sc = g[c] * rsqrtf(var + 1e-5f);
        scale[c] = sc;
        shift[c] = be[c] - m * sc;
    }
}

__global__ void bn_apply4_k(float4* __restrict__ x, const float* __restrict__ scale,
                            const float* __restrict__ shift, int C, int hwsh, int total4)
{
    int i = blockIdx.x * blockDim.x + threadIdx.x;
    if (i >= total4) return;
    int c = (i >> hwsh) % C;
    float s = scale[c], t = shift[c];
    float4 v = x[i];
    v.x = fmaxf(fmaf(v.x, s, t), 0.f);
    v.y = fmaxf(fmaf(v.y, s, t), 0.f);
    v.z = fmaxf(fmaf(v.z, s, t), 0.f);
    v.w = fmaxf(fmaf(v.w, s, t), 0.f);
    x[i] = v;
}

__global__ void cc_k(const float* __restrict__ cb, float* __restrict__ cc)
{
    int j = blockIdx.x * blockDim.x + threadIdx.x;
    if (j >= 256) return;
    double s = 0.0;
    const float* row = cb + (long)j * 256;
    for (int d = 0; d < 256; d++) {
        double v = (double)row[d];
        s += v * v;
    }
    cc[j] = (float)s;
}

// ---------------------------------------------------------------------------
// VQ with reference-exact fp32 distance emulation, code-pair fma2 packing.
// Each fma2 lane carries one code's full sequential chain (bit-identical to
// the scalar version); comparisons remain in ascending-code order.
// ---------------------------------------------------------------------------
__global__ void vq_exact_k(const float* __restrict__ h, const float* __restrict__ cb,
                           const float* __restrict__ cc, float* __restrict__ hq,
                           float* __restrict__ lossp)
{
    const int POS = 64;
    int b = blockIdx.x >> 2;
    int hw0 = (blockIdx.x & 3) * POS;
    int p = threadIdx.x;

    __shared__ float zs[256 * POS];
    __shared__ u64 cbs2[4 * 256];
    __shared__ float ccs[8];

    const float* hb = h + (long)b * 256 * 256 + hw0;
    for (int d = 0; d < 256; d++)
        zs[d * POS + p] = hb[d * 256 + p];
    __syncthreads();

    float zz = 0.f;
    for (int d = 0; d < 256; d++) {
        float z = zs[d * POS + p];
        zz = fmaf(z, z, zz);
    }

    float best = CUDART_INF_F;
    int bj = 0;

    for (int jc = 0; jc < 256; jc += 8) {
        __syncthreads();
        for (int t = p; t < 1024; t += POS) {
            int q4 = t >> 8, d = t & 255;
            cbs2[t] = pk(cb[(jc + 2 * q4) * 256 + d], cb[(jc + 2 * q4 + 1) * 256 + d]);
        }
        if (p < 8) ccs[p] = cc[jc + p];
        __syncthreads();

        u64 acc2[4];
#pragma unroll
        for (int q4 = 0; q4 < 4; q4++) acc2[q4] = pk(0.f, 0.f);

        for (int dc = 0; dc < 256; dc += 32) {
            u64 zp[32];
#pragma unroll
            for (int d = 0; d < 32; d++) {
                float z = zs[(dc + d) * POS + p];
                zp[d] = pk(z, z);
            }
#pragma unroll
            for (int q4 = 0; q4 < 4; q4++) {
#pragma unroll
                for (int d = 0; d < 32; d++)
                    fma2(acc2[q4], zp[d], cbs2[q4 * 256 + dc + d]);
            }
        }

#pragma unroll
        for (int q4 = 0; q4 < 4; q4++) {
            float alo, ahi;
            upk(acc2[q4], alo, ahi);
            float d2a = (zz + ccs[2 * q4]) - 2.0f * alo;
            if (d2a < best) { best = d2a; bj = jc + 2 * q4; }
            float d2b = (zz + ccs[2 * q4 + 1]) - 2.0f * ahi;
            if (d2b < best) { best = d2b; bj = jc + 2 * q4 + 1; }
        }
    }

    const float* crow = cb + (long)bj * 256;
    float* hqb = hq + (long)b * 256 * 256 + hw0;
    float l = 0.f;
    for (int d = 0; d < 256; d++) {
        float c = crow[d];
        hqb[d * 256 + p] = c;
        float diff = zs[d * POS + p] - c;
        l = fmaf(diff, diff, l);
    }
    lossp[b * 256 + hw0 + p] = l;
}

__global__ void loss_reduce_k(const float* __restrict__ lossp, float* __restrict__ out2)
{
    int tid = threadIdx.x;
    double s = 0.0;
    for (int i = tid; i < 32768; i += 1024) s += (double)lossp[i];
    __shared__ double sh[1024];
    sh[tid] = s;
    __syncthreads();
    for (int ofs = 512; ofs > 0; ofs >>= 1) {
        if (tid < ofs) sh[tid] += sh[tid + ofs];
        __syncthreads();
    }
    if (tid == 0) {
        float m = (float)(sh[0] / 32768.0);
        out2[0] = m;
        out2[1] = m;
    }
}

// ---------------------------------------------------------------------------
static inline int gridFor(int total, int block) { return (total + block - 1) / block; }

extern "C" void kernel_launch(void* const* d_in, const int* in_sizes, int n_in,
                              void* d_out, int out_size)
{
    const float* x        = (const float*)d_in[0];
    const float* codebook = (const float*)d_in[1];
    const float* e_w1 = (const float*)d_in[2];  const float* e_b1 = (const float*)d_in[3];
    const float* e_g1 = (const float*)d_in[4];  const float* e_be1 = (const float*)d_in[5];
    const float* e_w2 = (const float*)d_in[6];  const float* e_b2 = (const float*)d_in[7];
    const float* e_g2 = (const float*)d_in[8];  const float* e_be2 = (const float*)d_in[9];
    const float* e_w3 = (const float*)d_in[10]; const float* e_b3 = (const float*)d_in[11];
    const float* e_g3 = (const float*)d_in[12]; const float* e_be3 = (const float*)d_in[13];
    const float* e_w4 = (const float*)d_in[14]; const float* e_b4 = (const float*)d_in[15];
    const float* d_w1 = (const float*)d_in[16]; const float* d_b1 = (const float*)d_in[17];
    const float* d_g1 = (const float*)d_in[18]; const float* d_be1 = (const float*)d_in[19];
    const float* d_w2 = (const float*)d_in[20]; const float* d_b2 = (const float*)d_in[21];
    const float* d_g2 = (const float*)d_in[22]; const float* d_be2 = (const float*)d_in[23];
    const float* d_w3 = (const float*)d_in[24]; const float* d_b3 = (const float*)d_in[25];
    const float* d_g3 = (const float*)d_in[26]; const float* d_be3 = (const float*)d_in[27];
    const float* d_w4 = (const float*)d_in[28]; const float* d_b4 = (const float*)d_in[29];

    float* out = (float*)d_out;

    float *a1, *a2, *a3, *h4, *hq, *b1, *b2, *b3, *scale, *shift, *lossp, *cc;
    float *wt2, *wt3;
    u16 *b1h, *b1l, *b2h, *b2l, *wbh, *wbl, *w2bh, *w2bl;
    cudaGetSymbolAddress((void**)&a1, g_a1);
    cudaGetSymbolAddress((void**)&a2, g_a2);
    cudaGetSymbolAddress((void**)&a3, g_a3);
    cudaGetSymbolAddress((void**)&h4, g_h4);
    cudaGetSymbolAddress((void**)&hq, g_hq);
    cudaGetSymbolAddress((void**)&b1, g_d1);
    cudaGetSymbolAddress((void**)&b2, g_d2);
    cudaGetSymbolAddress((void**)&b3, g_d3);
    cudaGetSymbolAddress((void**)&scale, g_scale);
    cudaGetSymbolAddress((void**)&shift, g_shift);
    cudaGetSymbolAddress((void**)&lossp, g_lossp);
    cudaGetSymbolAddress((void**)&cc, g_cc);
    cudaGetSymbolAddress((void**)&wt2, g_wt2);
    cudaGetSymbolAddress((void**)&wt3, g_wt3);
    cudaGetSymbolAddress((void**)&b1h, g_b1h);
    cudaGetSymbolAddress((void**)&b1l, g_b1l);
    cudaGetSymbolAddress((void**)&b2h, g_b2h);
    cudaGetSymbolAddress((void**)&b2l, g_b2l);
    cudaGetSymbolAddress((void**)&wbh, g_wbh);
    cudaGetSymbolAddress((void**)&wbl, g_wbl);
    cudaGetSymbolAddress((void**)&w2bh, g_w2bh);
    cudaGetSymbolAddress((void**)&w2bl, g_w2bl);

    const int N = 128;

    const int SM_C2 = 2 * (4 * 18 * 66 + 4 * 16 * 64) * 4;
    const int SM_C3 = 2 * (4 * 18 * 34 + 4 * 16 * 64) * 4;
    const int SM_CL = 2 * (8 * 10 * 66) * 4;
    const int SM_M3 = 2 * 7168 * 4;    // 57344
    const int SM_M2 = 2 * 11520 * 4;   // 92160
    cudaFuncSetAttribute(convf3_k<32, 8, 4>, cudaFuncAttributeMaxDynamicSharedMemorySize, SM_C2);
    cudaFuncSetAttribute(convf3_k<16, 8, 4>, cudaFuncAttributeMaxDynamicSharedMemorySize, SM_C3);
    cudaFuncSetAttribute(convlast2_k, cudaFuncAttributeMaxDynamicSharedMemorySize, SM_CL);
    cudaFuncSetAttribute(convt_mma_k, cudaFuncAttributeMaxDynamicSharedMemorySize, SM_M3);
    cudaFuncSetAttribute(convt_mma2_k, cudaFuncAttributeMaxDynamicSharedMemorySize, SM_M2);

    // weight preps
    wtr_fwd_k<<<gridFor(64 * 128 * 16, 256), 256>>>(e_w2, wt2, 64, 128);
    wtr_fwd_k<<<gridFor(128 * 192 * 16, 256), 256>>>(e_w3, wt3, 128, 192);
    wsplit3n_k<<<gridFor(4 * 8 * 16 * 4 * 64, 256), 256>>>(d_w3, wbh, wbl);
    wsplit2n_k<<<gridFor(4 * 12 * 16 * 4 * 128, 256), 256>>>(d_w2, w2bh, w2bl);

    // ---- encoder ----
    convf1_k<<<dim3(16, N), 256>>>(x, e_w1, e_b1, a1);
    bn_stats_k<<<64, 1024>>>(a1, e_g1, e_be1, scale, shift, 64, N, 4096);
    bn_apply4_k<<<gridFor(N * 64 * 1024, 256), 256>>>((float4*)a1, scale, shift, 64, 10,
                                                      N * 64 * 1024);

    convf3_k<32, 8, 4><<<dim3(4 * 2, N), 256, SM_C2>>>(a1, wt2, e_b2, a2, 64, 128, 4);
    bn_stats_k<<<128, 1024>>>(a2, e_g2, e_be2, scale, shift, 128, N, 1024);
    bn_apply4_k<<<gridFor(N * 128 * 256, 256), 256>>>((float4*)a2, scale, shift, 128, 8,
                                                      N * 128 * 256);

    convf3_k<16, 8, 4><<<dim3(2 * 3, N), 256, SM_C3>>>(a2, wt3, e_b3, a3, 128, 192, 2);
    bn_stats_k<<<192, 1024>>>(a3, e_g3, e_be3, scale, shift, 192, N, 256);
    bn_apply4_k<<<gridFor(N * 192 * 64, 256), 256>>>((float4*)a3, scale, shift, 192, 6,
                                                     N * 192 * 64);

    gemm1x1_k<32, false><<<dim3(2 * 4, N), 256>>>(a3, e_w4, e_b4, h4, 192, 256, 256, 2);

    // ---- vector quantization ----
    cc_k<<<1, 256>>>(codebook, cc);
    vq_exact_k<<<512, 64>>>(h4, codebook, cc, hq, lossp);
    loss_reduce_k<<<1, 1024>>>(lossp, out + (out_size - 2));

    // ---- decoder ----
    gemm1x1_k<32, true><<<dim3(2 * 3, N), 256>>>(hq, d_w1, d_b1, b1, 256, 256, 192, 2);
    bn_stats_k<<<192, 1024>>>(b1, d_g1, d_be1, scale, shift, 192, N, 256);
    bn_apply_split_k<<<gridFor(N * 192 * 128, 256), 256>>>((const float2*)b1, scale, shift,
                                                           (u32*)b1h, (u32*)b1l,
                                                           192, 8, N * 192 * 128);

    convt_mma2_k<<<dim3(2, N, 4), 256, SM_M2>>>(b1h, b1l, w2bh, w2bl, d_b2, b2);
    bn_stats_k<<<128, 1024>>>(b2, d_g2, d_be2, scale, shift, 128, N, 1024);
    bn_apply_split_k<<<gridFor(N * 128 * 512, 256), 256>>>((const float2*)b2, scale, shift,
                                                           (u32*)b2h, (u32*)b2l,
                                                           128, 10, N * 128 * 512);

    convt_mma_k<<<dim3(8, N, 4), 256, SM_M3>>>(b2h, b2l, wbh, wbl, d_b3, b3);
    bn_stats_k<<<64, 1024>>>(b3, d_g3, d_be3, scale, shift, 64, N, 4096);
    bn_apply4_k<<<gridFor(N * 64 * 1024, 256), 256>>>((float4*)b3, scale, shift, 64, 10,
                                                      N * 64 * 1024);

    convlast2_k<<<dim3(8, N), 256, SM_CL>>>(b3, d_w4, d_b4, out);
}